// round 14
// baseline (speedup 1.0000x reference)
#include <cuda_runtime.h>
#include <math.h>

#define N_NODES 100000
#define N_EDGES 1000000
#define C 64
#define N_PAD 100032            // 1563 * 64
#define NB_TILES 1563           // node tiles of 64
#define PERSIST_BLOCKS 296      // 2 per SM (2 x 102.4KB smem <= 228KB)
#define BUILD_BLOCKS 98         // one wave: 98 <= 148 SMs
#define BUILD_THREADS 1024
#define TOT_T (BUILD_BLOCKS * BUILD_THREADS)   // 100352
#define EPT 10                  // edges per thread (10 * 100352 >= 1M)
#define FLAGBIT (1 << 30)

#define SW_STRIDE 68            // floats per weight row (transposed, padded)
#define WP_SZ (64 * SW_STRIDE)  // 4352 floats per matrix

typedef unsigned long long ull;

// ---------------- scratch (device globals; no allocation allowed) -----------
// g_deg / g_look / g_bar* must be zero at entry: zero at module load, and
// node_kernel<2>'s tail re-zeros them each call -> deterministic across calls.
// g_wp is fully rewritten by build_kernel phase 0 every call.
__device__ __align__(16) float g_mean[(size_t)N_PAD * C];
__device__ __align__(16) float g_h1  [(size_t)N_PAD * C];
__device__ __align__(16) float g_wp[4 * WP_SZ];   // [w1l | w1r | w2l | w2r] transposed
__device__ int g_deg[N_NODES];
__device__ int g_rowptr[N_NODES + 1];
__device__ int g_col[N_EDGES];
__device__ int g_look[BUILD_BLOCKS];
__device__ int g_bar1;
__device__ int g_bar2;

// ---------------- f32x2 packed FMA helpers ----------------------------------
__device__ __forceinline__ ull pk2(float lo, float hi) {
    ull r;
    asm("mov.b64 %0, {%1, %2};" : "=l"(r) : "f"(lo), "f"(hi));
    return r;
}
__device__ __forceinline__ ull fma2(ull a, ull b, ull c) {
    ull d;
    asm("fma.rn.f32x2 %0, %1, %2, %3;" : "=l"(d) : "l"(a), "l"(b), "l"(c));
    return d;
}
__device__ __forceinline__ void unpk2(ull v, float& lo, float& hi) {
    asm("mov.b64 {%0, %1}, %2;" : "=f"(lo), "=f"(hi) : "l"(v));
}

// ---------------- grid barrier (all blocks resident: one wave) ---------------
__device__ __forceinline__ void grid_bar(int* ctr) {
    __syncthreads();
    if (threadIdx.x == 0) {
        __threadfence();
        atomicAdd(ctr, 1);
        while (atomicAdd(ctr, 0) < BUILD_BLOCKS) { }
        __threadfence();
    }
    __syncthreads();
}

// ========================= cooperative CSR build + weight prep ===============
// Phase 0: blocks 0-3 transpose one weight matrix each into g_wp.
// Phase 1: degree count — atomicAdd return IS the edge's within-node rank.
// Phase 2: block scan + decoupled lookback -> g_rowptr.
// Phase 3: rankless fill: g_col[rowptr[dst] + rank] = src. Zero atomics.
__global__ void __launch_bounds__(BUILD_THREADS) build_kernel(
        const int* __restrict__ src, const int* __restrict__ dst,
        const float* __restrict__ w1l, const float* __restrict__ w1r,
        const float* __restrict__ w2l, const float* __restrict__ w2r) {
    int t = threadIdx.x;
    int b = blockIdx.x;
    int gtid = b * BUILD_THREADS + t;

    // ---- phase 0: weight transpose prep ----
    if (b < 4) {
        const float* W = (b == 0) ? w1l : (b == 1) ? w1r : (b == 2) ? w2l : w2r;
        float* Wp = g_wp + b * WP_SZ;
        #pragma unroll
        for (int i = t; i < 64 * 64; i += BUILD_THREADS) {
            int o = i >> 6, k = i & 63;
            Wp[k * SW_STRIDE + o] = W[i];
        }
    }

    // ---- phase 1: degree + rank ----
    int myDst[EPT];
    int myRank[EPT];
    #pragma unroll
    for (int k = 0; k < EPT; ++k) {
        int e = gtid + k * TOT_T;           // grid-strided: coalesced
        if (e < N_EDGES) {
            int d = dst[e];
            myDst[k] = d;
            myRank[k] = atomicAdd(&g_deg[d], 1);
        } else {
            myDst[k] = -1;
        }
    }
    grid_bar(&g_bar1);

    // ---- phase 2: scan ----
    {
        __shared__ int swarp[32];
        __shared__ int sprefix;
        int i = b * BUILD_THREADS + t;
        int lane = t & 31;
        int wid = t >> 5;

        int deg = (i < N_NODES) ? g_deg[i] : 0;

        int v = deg;
        #pragma unroll
        for (int off = 1; off < 32; off <<= 1) {
            int u = __shfl_up_sync(0xffffffffu, v, off);
            if (lane >= off) v += u;
        }
        if (lane == 31) swarp[wid] = v;
        __syncthreads();
        if (wid == 0) {
            int w = swarp[lane];
            #pragma unroll
            for (int off = 1; off < 32; off <<= 1) {
                int u = __shfl_up_sync(0xffffffffu, w, off);
                if (lane >= off) w += u;
            }
            swarp[lane] = w;
        }
        __syncthreads();
        int incl = v + (wid > 0 ? swarp[wid - 1] : 0);
        int total = swarp[31];

        if (t == 0) atomicExch(&g_look[b], total | FLAGBIT);
        if (wid == 0) {
            int run = 0;
            for (int base = 0; base < b; base += 32) {
                int idx = base + lane;
                int a = 0;
                if (idx < b) {
                    do { a = atomicAdd(&g_look[idx], 0); } while (!(a & FLAGBIT));
                    a &= ~FLAGBIT;
                }
                #pragma unroll
                for (int off = 16; off > 0; off >>= 1)
                    a += __shfl_xor_sync(0xffffffffu, a, off);
                run += a;
            }
            if (lane == 0) sprefix = run;
        }
        __syncthreads();

        if (i < N_NODES) {
            g_rowptr[i + 1] = sprefix + incl;
            if (i == 0) g_rowptr[0] = 0;
        }
    }
    grid_bar(&g_bar2);

    // ---- phase 3: rankless fill ----
    #pragma unroll
    for (int k = 0; k < EPT; ++k) {
        int e = gtid + k * TOT_T;
        if (e < N_EDGES) {
            int s = src[e];                 // coalesced load
            g_col[g_rowptr[myDst[k]] + myRank[k]] = s;
        }
    }
}

// ========================= mean aggregation (high-occupancy) =================
// 16 threads per node (one float4 chunk each), 256-thread blocks. At the LTS
// gather ceiling (~10TB/s effective); MUST stay separate from the GEMM (R10).
template <int LAYER>
__global__ void __launch_bounds__(256) agg_mean_kernel(const float* __restrict__ x_ext) {
    int idx = blockIdx.x * 256 + threadIdx.x;
    int n = idx >> 4;
    int c = idx & 15;
    if (n >= N_NODES) {
        ((float4*)g_mean)[(size_t)n * 16 + c] = make_float4(0.f, 0.f, 0.f, 0.f);
        return;
    }
    const float4* f4 = (LAYER == 1) ? (const float4*)x_ext : (const float4*)g_h1;
    int beg = g_rowptr[n];
    int end = g_rowptr[n + 1];
    float4 acc = make_float4(0.f, 0.f, 0.f, 0.f);
    int j = beg;
    for (; j + 1 < end; j += 2) {
        int s0 = g_col[j];
        int s1 = g_col[j + 1];
        float4 a = f4[(size_t)s0 * 16 + c];
        float4 b = f4[(size_t)s1 * 16 + c];
        acc.x += a.x + b.x; acc.y += a.y + b.y;
        acc.z += a.z + b.z; acc.w += a.w + b.w;
    }
    if (j < end) {
        int s0 = g_col[j];
        float4 a = f4[(size_t)s0 * 16 + c];
        acc.x += a.x; acc.y += a.y; acc.z += a.z; acc.w += a.w;
    }
    float inv = 1.0f / fmaxf((float)(end - beg), 1.0f);
    acc.x *= inv; acc.y *= inv; acc.z *= inv; acc.w *= inv;
    ((float4*)g_mean)[(size_t)n * 16 + c] = acc;
}

// ========================= persistent node GEMM ==============================
// 296 persistent blocks (2/SM), 128 threads, static tile loop. Weights staged
// ONCE per block; per tile: value staging + R8-proven fma2 mainloop.
#define SM_STRIDE 66            // u64 per node row (even -> 16B-aligned ull2)
#define SMEM_BYTES (2*64*SW_STRIDE*4 + 2*64*SM_STRIDE*8)   // 102400

template <int LAYER>
__global__ void __launch_bounds__(128) node_kernel(
        const float* __restrict__ x_ext,
        const float* __restrict__ bias,
        const float* __restrict__ w_out,
        const float* __restrict__ b_out,
        float* __restrict__ out) {
    extern __shared__ char smraw[];
    float* sWl = (float*)smraw;                       // [64][SW_STRIDE]
    float* sWr = sWl + 64 * SW_STRIDE;                // contiguous after sWl
    ull* sMd = (ull*)(sWr + 64 * SW_STRIDE);          // [64][SM_STRIDE]
    ull* sSd = sMd + 64 * SM_STRIDE;

    const float* selfF = (LAYER == 1) ? x_ext : (const float*)g_h1;

    int t = threadIdx.x;
    int og = t & 15;
    int ng = t >> 4;

    // ---- weight staging ONCE per block ----
    {
        const float4* srcw = (const float4*)(g_wp + (LAYER == 1 ? 0 : 2 * WP_SZ));
        float4* dstw = (float4*)sWl;
        #pragma unroll
        for (int i = 0; i < (2 * WP_SZ) / 4 / 128; ++i)   // 17 iters
            dstw[i * 128 + t] = srcw[i * 128 + t];
    }

    // hoisted per-thread constants
    float4 b4 = *(const float4*)&bias[og * 4];
    float4 wo;
    float bo = 0.f;
    if (LAYER == 2) {
        wo = *(const float4*)&w_out[og * 4];
        bo = b_out[0];
    }

    const ull* mrow = &sMd[(ng * 8) * SM_STRIDE];
    const ull* srow = &sSd[(ng * 8) * SM_STRIDE];

    for (int tile = blockIdx.x; tile < NB_TILES; tile += PERSIST_BLOCKS) {
        int base = tile * 64;

        // ---- value staging ----
        #pragma unroll
        for (int it = 0; it < 8; ++it) {
            int item = it * 128 + t;
            int n = item & 63;
            int c = item >> 6;
            int gn = base + n;
            int cn = (LAYER == 1) ? min(gn, N_NODES - 1) : gn;
            float4 m = ((const float4*)g_mean)[(size_t)gn * 16 + c];
            float4 s = ((const float4*)selfF)[(size_t)cn * 16 + c];
            ulonglong2* mp = (ulonglong2*)&sMd[n * SM_STRIDE + 4 * c];
            ulonglong2* sp = (ulonglong2*)&sSd[n * SM_STRIDE + 4 * c];
            ulonglong2 v;
            v.x = pk2(m.x, m.x); v.y = pk2(m.y, m.y);
            mp[0] = v;
            v.x = pk2(m.z, m.z); v.y = pk2(m.w, m.w);
            mp[1] = v;
            v.x = pk2(s.x, s.x); v.y = pk2(s.y, s.y);
            sp[0] = v;
            v.x = pk2(s.z, s.z); v.y = pk2(s.w, s.w);
            sp[1] = v;
        }
        __syncthreads();

        // ---- GEMM mainloop (R8-proven) ----
        ull acc[8][2];
        #pragma unroll
        for (int n = 0; n < 8; ++n) {
            acc[n][0] = pk2(b4.x, b4.y);
            acc[n][1] = pk2(b4.z, b4.w);
        }

        #pragma unroll 4
        for (int k = 0; k < C; k += 2) {
            ulonglong2 wl0 = *(const ulonglong2*)&sWl[k * SW_STRIDE + og * 4];
            ulonglong2 wl1 = *(const ulonglong2*)&sWl[(k + 1) * SW_STRIDE + og * 4];
            ulonglong2 wr0 = *(const ulonglong2*)&sWr[k * SW_STRIDE + og * 4];
            ulonglong2 wr1 = *(const ulonglong2*)&sWr[(k + 1) * SW_STRIDE + og * 4];
            {
                ulonglong2 mv[8];
                #pragma unroll
                for (int n = 0; n < 8; ++n)
                    mv[n] = *(const ulonglong2*)&mrow[n * SM_STRIDE + k];
                #pragma unroll
                for (int n = 0; n < 8; ++n) {
                    acc[n][0] = fma2(mv[n].x, wl0.x, acc[n][0]);
                    acc[n][1] = fma2(mv[n].x, wl0.y, acc[n][1]);
                }
                #pragma unroll
                for (int n = 0; n < 8; ++n) {
                    acc[n][0] = fma2(mv[n].y, wl1.x, acc[n][0]);
                    acc[n][1] = fma2(mv[n].y, wl1.y, acc[n][1]);
                }
            }
            {
                ulonglong2 sv[8];
                #pragma unroll
                for (int n = 0; n < 8; ++n)
                    sv[n] = *(const ulonglong2*)&srow[n * SM_STRIDE + k];
                #pragma unroll
                for (int n = 0; n < 8; ++n) {
                    acc[n][0] = fma2(sv[n].x, wr0.x, acc[n][0]);
                    acc[n][1] = fma2(sv[n].x, wr0.y, acc[n][1]);
                }
                #pragma unroll
                for (int n = 0; n < 8; ++n) {
                    acc[n][0] = fma2(sv[n].y, wr1.x, acc[n][0]);
                    acc[n][1] = fma2(sv[n].y, wr1.y, acc[n][1]);
                }
            }
        }

        // ---- epilogue ----
        if (LAYER == 1) {
            #pragma unroll
            for (int n = 0; n < 8; ++n) {
                float4 r;
                unpk2(acc[n][0], r.x, r.y);
                unpk2(acc[n][1], r.z, r.w);
                r.x = fmaxf(r.x, 0.f); r.y = fmaxf(r.y, 0.f);
                r.z = fmaxf(r.z, 0.f); r.w = fmaxf(r.w, 0.f);
                int gn = base + ng * 8 + n;
                ((float4*)g_h1)[(size_t)gn * 16 + og] = r;   // gn < N_PAD
            }
        } else {
            #pragma unroll
            for (int n = 0; n < 8; ++n) {
                float r0, r1, r2, r3;
                unpk2(acc[n][0], r0, r1);
                unpk2(acc[n][1], r2, r3);
                r0 = fmaxf(r0, 0.f); r1 = fmaxf(r1, 0.f);
                r2 = fmaxf(r2, 0.f); r3 = fmaxf(r3, 0.f);
                float p = r0 * wo.x + r1 * wo.y + r2 * wo.z + r3 * wo.w;
                p += __shfl_xor_sync(0xffffffffu, p, 1);
                p += __shfl_xor_sync(0xffffffffu, p, 2);
                p += __shfl_xor_sync(0xffffffffu, p, 4);
                p += __shfl_xor_sync(0xffffffffu, p, 8);
                if (og == 0) {
                    int gn = base + ng * 8 + n;
                    if (gn < N_NODES) {
                        out[gn] = 1.0f / (1.0f + expf(-(p + bo)));
                    }
                }
            }
        }
        __syncthreads();   // all smem reads done before next tile's staging
    }

    // ---- tail (LAYER 2): re-zero build state for the next call ----
    if (LAYER == 2) {
        for (int idx = blockIdx.x * 128 + t; idx < N_NODES; idx += PERSIST_BLOCKS * 128)
            g_deg[idx] = 0;
        int idx = blockIdx.x * 128 + t;
        if (idx < BUILD_BLOCKS) g_look[idx] = 0;
        if (idx == 0) { g_bar1 = 0; g_bar2 = 0; }
    }
}

// ========================= launch ============================================
extern "C" void kernel_launch(void* const* d_in, const int* in_sizes, int n_in,
                              void* d_out, int out_size) {
    const float* x     = (const float*)d_in[0];
    const int*   ei    = (const int*)  d_in[1];
    const float* w1_l  = (const float*)d_in[2];
    const float* b1    = (const float*)d_in[3];
    const float* w1_r  = (const float*)d_in[4];
    const float* w2_l  = (const float*)d_in[5];
    const float* b2    = (const float*)d_in[6];
    const float* w2_r  = (const float*)d_in[7];
    const float* w_out = (const float*)d_in[8];
    const float* b_out = (const float*)d_in[9];
    float* out = (float*)d_out;

    const int* src = ei;
    const int* dst = ei + N_EDGES;

    cudaFuncSetAttribute(node_kernel<1>, cudaFuncAttributeMaxDynamicSharedMemorySize, SMEM_BYTES);
    cudaFuncSetAttribute(node_kernel<2>, cudaFuncAttributeMaxDynamicSharedMemorySize, SMEM_BYTES);

    const int AB = (N_PAD * 16) / 256;               // 6252

    // ---- CSR build + weight prep: one cooperative kernel ----
    build_kernel<<<BUILD_BLOCKS, BUILD_THREADS>>>(src, dst, w1_l, w1_r, w2_l, w2_r);

    // ---- layer 1 ----
    agg_mean_kernel<1><<<AB, 256>>>(x);
    node_kernel<1><<<PERSIST_BLOCKS, 128, SMEM_BYTES>>>(x, b1, w_out, b_out, out);

    // ---- layer 2 (+ fused sigmoid head + state re-zero) ----
    agg_mean_kernel<2><<<AB, 256>>>(x);
    node_kernel<2><<<PERSIST_BLOCKS, 128, SMEM_BYTES>>>(x, b2, w_out, b_out, out);
}

// round 15
// speedup vs baseline: 1.0784x; 1.0784x over previous
#include <cuda_runtime.h>
#include <math.h>

#define N_NODES 100000
#define N_EDGES 1000000
#define C 64
#define N_PAD 100032            // 1563 * 64
#define BUILD_BLOCKS 98         // one wave: 98 <= 148 SMs
#define BUILD_THREADS 1024
#define TOT_T (BUILD_BLOCKS * BUILD_THREADS)   // 100352
#define EPT 10                  // edges per thread (10 * 100352 >= 1M)
#define FLAGBIT (1 << 30)

#define SW_STRIDE 68            // floats per weight row (transposed, padded)
#define WP_SZ (64 * SW_STRIDE)  // 4352 floats per matrix

typedef unsigned long long ull;

// ---------------- scratch (device globals; no allocation allowed) -----------
// g_deg / g_look / g_bar* must be zero at entry: zero at module load, and
// node_kernel<2>'s tail re-zeros them each call -> deterministic across calls.
// g_wp is fully rewritten by build_kernel phase 0 every call.
__device__ __align__(16) float g_mean[(size_t)N_PAD * C];
__device__ __align__(16) float g_h1  [(size_t)N_PAD * C];
__device__ __align__(16) float g_wp[4 * WP_SZ];   // [w1l | w1r | w2l | w2r] transposed
__device__ int g_deg[N_NODES];
__device__ int g_rowptr[N_NODES + 1];
__device__ int g_col[N_EDGES];
__device__ int g_look[BUILD_BLOCKS];
__device__ int g_bar1;
__device__ int g_bar2;

// ---------------- f32x2 packed FMA helpers ----------------------------------
__device__ __forceinline__ ull pk2(float lo, float hi) {
    ull r;
    asm("mov.b64 %0, {%1, %2};" : "=l"(r) : "f"(lo), "f"(hi));
    return r;
}
__device__ __forceinline__ ull fma2(ull a, ull b, ull c) {
    ull d;
    asm("fma.rn.f32x2 %0, %1, %2, %3;" : "=l"(d) : "l"(a), "l"(b), "l"(c));
    return d;
}
__device__ __forceinline__ void unpk2(ull v, float& lo, float& hi) {
    asm("mov.b64 {%0, %1}, %2;" : "=f"(lo), "=f"(hi) : "l"(v));
}

// ---------------- grid barrier (all blocks resident: one wave) ---------------
__device__ __forceinline__ void grid_bar(int* ctr) {
    __syncthreads();
    if (threadIdx.x == 0) {
        __threadfence();
        atomicAdd(ctr, 1);
        while (atomicAdd(ctr, 0) < BUILD_BLOCKS) { }
        __threadfence();
    }
    __syncthreads();
}

// ========================= cooperative CSR build + weight prep ===============
// Phase 0: blocks 0-3 transpose one weight matrix each into g_wp.
// Phase 1: degree count — atomicAdd return IS the edge's within-node rank.
// Phase 2: block scan + decoupled lookback -> g_rowptr.
// Phase 3: rankless fill: g_col[rowptr[dst] + rank] = src. Zero atomics.
__global__ void __launch_bounds__(BUILD_THREADS) build_kernel(
        const int* __restrict__ src, const int* __restrict__ dst,
        const float* __restrict__ w1l, const float* __restrict__ w1r,
        const float* __restrict__ w2l, const float* __restrict__ w2r) {
    int t = threadIdx.x;
    int b = blockIdx.x;
    int gtid = b * BUILD_THREADS + t;

    // ---- phase 0: weight transpose prep ----
    if (b < 4) {
        const float* W = (b == 0) ? w1l : (b == 1) ? w1r : (b == 2) ? w2l : w2r;
        float* Wp = g_wp + b * WP_SZ;
        #pragma unroll
        for (int i = t; i < 64 * 64; i += BUILD_THREADS) {
            int o = i >> 6, k = i & 63;
            Wp[k * SW_STRIDE + o] = W[i];
        }
    }

    // ---- phase 1: degree + rank ----
    int myDst[EPT];
    int myRank[EPT];
    #pragma unroll
    for (int k = 0; k < EPT; ++k) {
        int e = gtid + k * TOT_T;           // grid-strided: coalesced
        if (e < N_EDGES) {
            int d = dst[e];
            myDst[k] = d;
            myRank[k] = atomicAdd(&g_deg[d], 1);
        } else {
            myDst[k] = -1;
        }
    }
    grid_bar(&g_bar1);

    // ---- phase 2: scan ----
    {
        __shared__ int swarp[32];
        __shared__ int sprefix;
        int i = b * BUILD_THREADS + t;
        int lane = t & 31;
        int wid = t >> 5;

        int deg = (i < N_NODES) ? g_deg[i] : 0;

        int v = deg;
        #pragma unroll
        for (int off = 1; off < 32; off <<= 1) {
            int u = __shfl_up_sync(0xffffffffu, v, off);
            if (lane >= off) v += u;
        }
        if (lane == 31) swarp[wid] = v;
        __syncthreads();
        if (wid == 0) {
            int w = swarp[lane];
            #pragma unroll
            for (int off = 1; off < 32; off <<= 1) {
                int u = __shfl_up_sync(0xffffffffu, w, off);
                if (lane >= off) w += u;
            }
            swarp[lane] = w;
        }
        __syncthreads();
        int incl = v + (wid > 0 ? swarp[wid - 1] : 0);
        int total = swarp[31];

        if (t == 0) atomicExch(&g_look[b], total | FLAGBIT);
        if (wid == 0) {
            int run = 0;
            for (int base = 0; base < b; base += 32) {
                int idx = base + lane;
                int a = 0;
                if (idx < b) {
                    do { a = atomicAdd(&g_look[idx], 0); } while (!(a & FLAGBIT));
                    a &= ~FLAGBIT;
                }
                #pragma unroll
                for (int off = 16; off > 0; off >>= 1)
                    a += __shfl_xor_sync(0xffffffffu, a, off);
                run += a;
            }
            if (lane == 0) sprefix = run;
        }
        __syncthreads();

        if (i < N_NODES) {
            g_rowptr[i + 1] = sprefix + incl;
            if (i == 0) g_rowptr[0] = 0;
        }
    }
    grid_bar(&g_bar2);

    // ---- phase 3: rankless fill ----
    #pragma unroll
    for (int k = 0; k < EPT; ++k) {
        int e = gtid + k * TOT_T;
        if (e < N_EDGES) {
            int s = src[e];                 // coalesced load
            g_col[g_rowptr[myDst[k]] + myRank[k]] = s;
        }
    }
}

// ========================= mean aggregation (high-occupancy) =================
// 16 threads per node (one float4 chunk each), 256-thread blocks. At the LTS
// gather ceiling (~10TB/s effective); MUST stay separate from the GEMM (R10).
template <int LAYER>
__global__ void __launch_bounds__(256) agg_mean_kernel(const float* __restrict__ x_ext) {
    int idx = blockIdx.x * 256 + threadIdx.x;
    int n = idx >> 4;
    int c = idx & 15;
    if (n >= N_NODES) {
        ((float4*)g_mean)[(size_t)n * 16 + c] = make_float4(0.f, 0.f, 0.f, 0.f);
        return;
    }
    const float4* f4 = (LAYER == 1) ? (const float4*)x_ext : (const float4*)g_h1;
    int beg = g_rowptr[n];
    int end = g_rowptr[n + 1];
    float4 acc = make_float4(0.f, 0.f, 0.f, 0.f);
    int j = beg;
    for (; j + 1 < end; j += 2) {
        int s0 = g_col[j];
        int s1 = g_col[j + 1];
        float4 a = f4[(size_t)s0 * 16 + c];
        float4 b = f4[(size_t)s1 * 16 + c];
        acc.x += a.x + b.x; acc.y += a.y + b.y;
        acc.z += a.z + b.z; acc.w += a.w + b.w;
    }
    if (j < end) {
        int s0 = g_col[j];
        float4 a = f4[(size_t)s0 * 16 + c];
        acc.x += a.x; acc.y += a.y; acc.z += a.z; acc.w += a.w;
    }
    float inv = 1.0f / fmaxf((float)(end - beg), 1.0f);
    acc.x *= inv; acc.y *= inv; acc.z *= inv; acc.w *= inv;
    ((float4*)g_mean)[(size_t)n * 16 + c] = acc;
}

// ========================= node GEMM (R13 + coalesced value staging) =========
// 128 threads, 64 nodes/block (launch-pipelined — persistent regressed, R14).
// Staging mapping n = item>>4, c = item&15: 16 consecutive lanes read one
// node's contiguous 256B row -> 4 lines/LDG.128 instead of 32 (8x fewer
// L1tex wavefronts). Mainloop byte-identical to R8/R13.
#define SM_STRIDE 66            // u64 per node row (even -> 16B-aligned ull2)
#define SMEM_BYTES (2*64*SW_STRIDE*4 + 2*64*SM_STRIDE*8)   // 102400

template <int LAYER>
__global__ void __launch_bounds__(128) node_kernel(
        const float* __restrict__ x_ext,
        const float* __restrict__ bias,
        const float* __restrict__ w_out,
        const float* __restrict__ b_out,
        float* __restrict__ out) {
    extern __shared__ char smraw[];
    float* sWl = (float*)smraw;                       // [64][SW_STRIDE]
    float* sWr = sWl + 64 * SW_STRIDE;                // contiguous after sWl
    ull* sMd = (ull*)(sWr + 64 * SW_STRIDE);          // [64][SM_STRIDE]
    ull* sSd = sMd + 64 * SM_STRIDE;

    const float* selfF = (LAYER == 1) ? x_ext : (const float*)g_h1;

    int t = threadIdx.x;
    int og = t & 15;
    int ng = t >> 4;
    int base = blockIdx.x * 64;

    // ---- weight staging: straight float4 copy of pre-transposed g_wp ----
    {
        const float4* srcw = (const float4*)(g_wp + (LAYER == 1 ? 0 : 2 * WP_SZ));
        float4* dstw = (float4*)sWl;
        #pragma unroll
        for (int i = 0; i < (2 * WP_SZ) / 4 / 128; ++i)   // 17 iters
            dstw[i * 128 + t] = srcw[i * 128 + t];
    }

    // ---- value staging: COALESCED mapping (one node row per 16 lanes) ----
    #pragma unroll
    for (int it = 0; it < 8; ++it) {
        int item = it * 128 + t;
        int n = item >> 4;                  // node 0..63
        int c = item & 15;                  // float4 chunk 0..15
        int gn = base + n;
        int cn = (LAYER == 1) ? min(gn, N_NODES - 1) : gn;
        float4 m = ((const float4*)g_mean)[(size_t)gn * 16 + c];
        float4 s = ((const float4*)selfF)[(size_t)cn * 16 + c];
        ulonglong2* mp = (ulonglong2*)&sMd[n * SM_STRIDE + 4 * c];
        ulonglong2* sp = (ulonglong2*)&sSd[n * SM_STRIDE + 4 * c];
        ulonglong2 v;
        v.x = pk2(m.x, m.x); v.y = pk2(m.y, m.y);
        mp[0] = v;
        v.x = pk2(m.z, m.z); v.y = pk2(m.w, m.w);
        mp[1] = v;
        v.x = pk2(s.x, s.x); v.y = pk2(s.y, s.y);
        sp[0] = v;
        v.x = pk2(s.z, s.z); v.y = pk2(s.w, s.w);
        sp[1] = v;
    }
    __syncthreads();

    float4 b4 = *(const float4*)&bias[og * 4];
    ull acc[8][2];
    #pragma unroll
    for (int n = 0; n < 8; ++n) {
        acc[n][0] = pk2(b4.x, b4.y);
        acc[n][1] = pk2(b4.z, b4.w);
    }

    const ull* mrow = &sMd[(ng * 8) * SM_STRIDE];
    const ull* srow = &sSd[(ng * 8) * SM_STRIDE];

    #pragma unroll 4
    for (int k = 0; k < C; k += 2) {
        ulonglong2 wl0 = *(const ulonglong2*)&sWl[k * SW_STRIDE + og * 4];
        ulonglong2 wl1 = *(const ulonglong2*)&sWl[(k + 1) * SW_STRIDE + og * 4];
        ulonglong2 wr0 = *(const ulonglong2*)&sWr[k * SW_STRIDE + og * 4];
        ulonglong2 wr1 = *(const ulonglong2*)&sWr[(k + 1) * SW_STRIDE + og * 4];
        {
            ulonglong2 mv[8];
            #pragma unroll
            for (int n = 0; n < 8; ++n)
                mv[n] = *(const ulonglong2*)&mrow[n * SM_STRIDE + k];
            #pragma unroll
            for (int n = 0; n < 8; ++n) {
                acc[n][0] = fma2(mv[n].x, wl0.x, acc[n][0]);
                acc[n][1] = fma2(mv[n].x, wl0.y, acc[n][1]);
            }
            #pragma unroll
            for (int n = 0; n < 8; ++n) {
                acc[n][0] = fma2(mv[n].y, wl1.x, acc[n][0]);
                acc[n][1] = fma2(mv[n].y, wl1.y, acc[n][1]);
            }
        }
        {
            ulonglong2 sv[8];
            #pragma unroll
            for (int n = 0; n < 8; ++n)
                sv[n] = *(const ulonglong2*)&srow[n * SM_STRIDE + k];
            #pragma unroll
            for (int n = 0; n < 8; ++n) {
                acc[n][0] = fma2(sv[n].x, wr0.x, acc[n][0]);
                acc[n][1] = fma2(sv[n].x, wr0.y, acc[n][1]);
            }
            #pragma unroll
            for (int n = 0; n < 8; ++n) {
                acc[n][0] = fma2(sv[n].y, wr1.x, acc[n][0]);
                acc[n][1] = fma2(sv[n].y, wr1.y, acc[n][1]);
            }
        }
    }

    if (LAYER == 1) {
        #pragma unroll
        for (int n = 0; n < 8; ++n) {
            float4 r;
            unpk2(acc[n][0], r.x, r.y);
            unpk2(acc[n][1], r.z, r.w);
            r.x = fmaxf(r.x, 0.f); r.y = fmaxf(r.y, 0.f);
            r.z = fmaxf(r.z, 0.f); r.w = fmaxf(r.w, 0.f);
            int gn = base + ng * 8 + n;
            ((float4*)g_h1)[(size_t)gn * 16 + og] = r;   // gn < N_PAD
        }
    } else {
        float4 wo = *(const float4*)&w_out[og * 4];
        float bo = b_out[0];
        #pragma unroll
        for (int n = 0; n < 8; ++n) {
            float r0, r1, r2, r3;
            unpk2(acc[n][0], r0, r1);
            unpk2(acc[n][1], r2, r3);
            r0 = fmaxf(r0, 0.f); r1 = fmaxf(r1, 0.f);
            r2 = fmaxf(r2, 0.f); r3 = fmaxf(r3, 0.f);
            float p = r0 * wo.x + r1 * wo.y + r2 * wo.z + r3 * wo.w;
            p += __shfl_xor_sync(0xffffffffu, p, 1);
            p += __shfl_xor_sync(0xffffffffu, p, 2);
            p += __shfl_xor_sync(0xffffffffu, p, 4);
            p += __shfl_xor_sync(0xffffffffu, p, 8);
            if (og == 0) {
                int gn = base + ng * 8 + n;
                if (gn < N_NODES) {
                    out[gn] = 1.0f / (1.0f + expf(-(p + bo)));
                }
            }
        }
        // ---- tail: re-zero build state for the next call ----
        int idx = blockIdx.x * 128 + t;          // 1563*128 = 200064 >= N_NODES
        if (idx < N_NODES) g_deg[idx] = 0;
        if (idx < BUILD_BLOCKS) g_look[idx] = 0;
        if (idx == 0) { g_bar1 = 0; g_bar2 = 0; }
    }
}

// ========================= launch ============================================
extern "C" void kernel_launch(void* const* d_in, const int* in_sizes, int n_in,
                              void* d_out, int out_size) {
    const float* x     = (const float*)d_in[0];
    const int*   ei    = (const int*)  d_in[1];
    const float* w1_l  = (const float*)d_in[2];
    const float* b1    = (const float*)d_in[3];
    const float* w1_r  = (const float*)d_in[4];
    const float* w2_l  = (const float*)d_in[5];
    const float* b2    = (const float*)d_in[6];
    const float* w2_r  = (const float*)d_in[7];
    const float* w_out = (const float*)d_in[8];
    const float* b_out = (const float*)d_in[9];
    float* out = (float*)d_out;

    const int* src = ei;
    const int* dst = ei + N_EDGES;

    cudaFuncSetAttribute(node_kernel<1>, cudaFuncAttributeMaxDynamicSharedMemorySize, SMEM_BYTES);
    cudaFuncSetAttribute(node_kernel<2>, cudaFuncAttributeMaxDynamicSharedMemorySize, SMEM_BYTES);

    const int AB = (N_PAD * 16) / 256;               // 6252
    const int NB = N_PAD / 64;                       // 1563

    // ---- CSR build + weight prep: one cooperative kernel ----
    build_kernel<<<BUILD_BLOCKS, BUILD_THREADS>>>(src, dst, w1_l, w1_r, w2_l, w2_r);

    // ---- layer 1 ----
    agg_mean_kernel<1><<<AB, 256>>>(x);
    node_kernel<1><<<NB, 128, SMEM_BYTES>>>(x, b1, w_out, b_out, out);

    // ---- layer 2 (+ fused sigmoid head + state re-zero) ----
    agg_mean_kernel<2><<<AB, 256>>>(x);
    node_kernel<2><<<NB, 128, SMEM_BYTES>>>(x, b2, w_out, b_out, out);
}